// round 1
// baseline (speedup 1.0000x reference)
#include <cuda_runtime.h>
#include <cstdint>

// Problem constants (fixed by the dataset)
constexpr int NN = 100000;   // nodes
constexpr int EE = 1600000;  // edges
constexpr int RR = 8;        // relations
constexpr int DD = 64;       // hidden
constexpr int CC = 576;      // 8*64 relation cols + 64 Wroot cols
constexpr int SCAN_BLOCKS = (NN + 1023) / 1024;  // 98

// ---------------- scratch (static device allocations; no cudaMalloc) -------
__device__ float g_ha[(size_t)NN * DD];       // h after embedding / layer outputs
__device__ float g_hb[(size_t)NN * DD];
__device__ float g_xr[(size_t)NN * CC];       // per-node relation-transformed features
__device__ int   g_rowptr[NN + 1];
__device__ int   g_fill[NN];
__device__ int   g_cntR[NN * RR];
__device__ float g_invcnt[NN * RR];
__device__ int   g_col[EE];                   // packed: src | (et<<17)
__device__ int   g_bsum[128];

// ---------------- h0 = node_emb + type_emb[node_type] + MLP(props) ---------
__global__ void k_h0(const int* __restrict__ node_type,
                     const float* __restrict__ props,
                     const float* __restrict__ node_emb,
                     const float* __restrict__ type_emb,
                     const float* __restrict__ pw1, const float* __restrict__ pb1,
                     const float* __restrict__ pw2, const float* __restrict__ pb2)
{
    __shared__ float sw1[32 * 64];
    __shared__ float sw2[64 * 64];
    __shared__ float sb1[64];
    __shared__ float sb2[64];
    __shared__ float ste[16 * 64];
    for (int i = threadIdx.x; i < 32 * 64; i += blockDim.x) sw1[i] = pw1[i];
    for (int i = threadIdx.x; i < 64 * 64; i += blockDim.x) sw2[i] = pw2[i];
    for (int i = threadIdx.x; i < 64; i += blockDim.x) { sb1[i] = pb1[i]; sb2[i] = pb2[i]; }
    for (int i = threadIdx.x; i < 16 * 64; i += blockDim.x) ste[i] = type_emb[i];
    __syncthreads();

    int lane = threadIdx.x & 31;
    int warp = (blockIdx.x * blockDim.x + threadIdx.x) >> 5;
    int nwarps = (gridDim.x * blockDim.x) >> 5;

    for (int n = warp; n < NN; n += nwarps) {
        float pv = props[n * 32 + lane];          // lane k holds props[n][k]
        float2 t = { sb1[2 * lane], sb1[2 * lane + 1] };
        #pragma unroll
        for (int k = 0; k < 32; k++) {
            float a = __shfl_sync(0xffffffffu, pv, k);
            float2 w = *(const float2*)&sw1[k * 64 + 2 * lane];
            t.x = fmaf(a, w.x, t.x);
            t.y = fmaf(a, w.y, t.y);
        }
        t.x = fmaxf(t.x, 0.f); t.y = fmaxf(t.y, 0.f);
        float2 o = { sb2[2 * lane], sb2[2 * lane + 1] };
        #pragma unroll
        for (int k = 0; k < 64; k++) {
            float a = __shfl_sync(0xffffffffu, (k & 1) ? t.y : t.x, k >> 1);
            float2 w = *(const float2*)&sw2[k * 64 + 2 * lane];
            o.x = fmaf(a, w.x, o.x);
            o.y = fmaf(a, w.y, o.y);
        }
        int nt = node_type[n];
        float2 e  = *(const float2*)&node_emb[(size_t)n * 64 + 2 * lane];
        float2 te = *(const float2*)&ste[nt * 64 + 2 * lane];
        o.x += e.x + te.x;
        o.y += e.y + te.y;
        *(float2*)&g_ha[(size_t)n * 64 + 2 * lane] = o;
    }
}

// ---------------- CSR build -------------------------------------------------
__global__ void k_zero()
{
    int total = NN * RR + NN;
    for (int i = blockIdx.x * blockDim.x + threadIdx.x; i < total; i += gridDim.x * blockDim.x) {
        if (i < NN * RR) g_cntR[i] = 0;
        else             g_fill[i - NN * RR] = 0;
    }
}

__global__ void k_count(const int* __restrict__ ei, const int* __restrict__ et)
{
    for (int e = blockIdx.x * blockDim.x + threadIdx.x; e < EE; e += gridDim.x * blockDim.x) {
        int d = ei[EE + e];
        int r = et[e];
        atomicAdd(&g_cntR[d * RR + r], 1);
    }
}

__global__ void k_bsum()
{
    int n = blockIdx.x * 1024 + threadIdx.x;
    int s = 0;
    if (n < NN) {
        #pragma unroll
        for (int r = 0; r < RR; r++) s += g_cntR[n * RR + r];
    }
    __shared__ int sh[32];
    #pragma unroll
    for (int o = 16; o > 0; o >>= 1) s += __shfl_down_sync(0xffffffffu, s, o);
    if ((threadIdx.x & 31) == 0) sh[threadIdx.x >> 5] = s;
    __syncthreads();
    if (threadIdx.x < 32) {
        int v = sh[threadIdx.x];
        #pragma unroll
        for (int o = 16; o > 0; o >>= 1) v += __shfl_down_sync(0xffffffffu, v, o);
        if (threadIdx.x == 0) g_bsum[blockIdx.x] = v;
    }
}

__global__ void k_sscan()
{
    int acc = 0;
    for (int i = 0; i < SCAN_BLOCKS; i++) {
        int v = g_bsum[i];
        g_bsum[i] = acc;
        acc += v;
    }
}

__global__ void k_scan()
{
    int n = blockIdx.x * 1024 + threadIdx.x;
    int c[RR];
    int s = 0;
    if (n < NN) {
        #pragma unroll
        for (int r = 0; r < RR; r++) { c[r] = g_cntR[n * RR + r]; s += c[r]; }
    }
    int lane = threadIdx.x & 31, w = threadIdx.x >> 5;
    int incl = s;
    #pragma unroll
    for (int o = 1; o < 32; o <<= 1) {
        int v = __shfl_up_sync(0xffffffffu, incl, o);
        if (lane >= o) incl += v;
    }
    __shared__ int wsum[32];
    if (lane == 31) wsum[w] = incl;
    __syncthreads();
    if (threadIdx.x < 32) {
        int v = wsum[threadIdx.x];
        int iv = v;
        #pragma unroll
        for (int o = 1; o < 32; o <<= 1) {
            int u = __shfl_up_sync(0xffffffffu, iv, o);
            if (threadIdx.x >= o) iv += u;
        }
        wsum[threadIdx.x] = iv - v;   // exclusive scan of warp totals
    }
    __syncthreads();
    int excl = (incl - s) + wsum[w] + g_bsum[blockIdx.x];
    if (n < NN) {
        g_rowptr[n] = excl;
        #pragma unroll
        for (int r = 0; r < RR; r++)
            g_invcnt[n * RR + r] = 1.0f / (float)(c[r] > 1 ? c[r] : 1);
        if (n == NN - 1) g_rowptr[NN] = excl + s;
    }
}

__global__ void k_place(const int* __restrict__ ei, const int* __restrict__ et)
{
    for (int e = blockIdx.x * blockDim.x + threadIdx.x; e < EE; e += gridDim.x * blockDim.x) {
        int d = ei[EE + e];
        int r = et[e];
        int s = ei[e];
        int pos = g_rowptr[d] + atomicAdd(&g_fill[d], 1);
        g_col[pos] = s | (r << 17);
    }
}

// ---------------- per-layer GEMM: xr[N,576] = h @ [Wflat | Wroot] -----------
#define GEMM_BM 128
__global__ void __launch_bounds__(256) k_gemm(int layer,
                                              const float* __restrict__ W,
                                              const float* __restrict__ Wroot)
{
    const float* __restrict__ h_in = (layer == 0) ? g_ha : g_hb;
    __shared__ float As[GEMM_BM][33];   // K staged in 32-wide chunks, +1 pad
    __shared__ float Bs[64][64];

    int t  = threadIdx.x;
    int bx = blockIdx.x, by = blockIdx.y;
    int mbase = bx * GEMM_BM;

    // Load B tile (one relation's 64x64 W, or Wroot for by==8)
    const float* Bsrc = (by < 8) ? (W + (size_t)by * 4096) : Wroot;
    float* bsf = &Bs[0][0];
    for (int i = t; i < 4096; i += 256) bsf[i] = Bsrc[i];

    int tn = t & 7;      // 8 col-groups of 8
    int tm = t >> 3;     // 32 row-groups of 4

    float acc[4][8];
    #pragma unroll
    for (int i = 0; i < 4; i++)
        #pragma unroll
        for (int j = 0; j < 8; j++) acc[i][j] = 0.f;

    #pragma unroll
    for (int kt = 0; kt < 64; kt += 32) {
        __syncthreads();
        for (int i = t; i < GEMM_BM * 32; i += 256) {
            int m = i >> 5, kk = i & 31;
            int gm = mbase + m;
            As[m][kk] = (gm < NN) ? h_in[(size_t)gm * 64 + kt + kk] : 0.f;
        }
        __syncthreads();
        #pragma unroll 8
        for (int kk = 0; kk < 32; kk++) {
            int k = kt + kk;
            float a0 = As[tm * 4 + 0][kk];
            float a1 = As[tm * 4 + 1][kk];
            float a2 = As[tm * 4 + 2][kk];
            float a3 = As[tm * 4 + 3][kk];
            float4 b0 = *(const float4*)&Bs[k][tn * 8];
            float4 b1 = *(const float4*)&Bs[k][tn * 8 + 4];
            #define FMA_ROW(i, a) \
                acc[i][0] = fmaf(a, b0.x, acc[i][0]); acc[i][1] = fmaf(a, b0.y, acc[i][1]); \
                acc[i][2] = fmaf(a, b0.z, acc[i][2]); acc[i][3] = fmaf(a, b0.w, acc[i][3]); \
                acc[i][4] = fmaf(a, b1.x, acc[i][4]); acc[i][5] = fmaf(a, b1.y, acc[i][5]); \
                acc[i][6] = fmaf(a, b1.z, acc[i][6]); acc[i][7] = fmaf(a, b1.w, acc[i][7]);
            FMA_ROW(0, a0)
            FMA_ROW(1, a1)
            FMA_ROW(2, a2)
            FMA_ROW(3, a3)
            #undef FMA_ROW
        }
    }

    int cbase = by * 64 + tn * 8;
    #pragma unroll
    for (int i = 0; i < 4; i++) {
        int gm = mbase + tm * 4 + i;
        if (gm < NN) {
            size_t off = (size_t)gm * CC + cbase;
            float4 v0 = { acc[i][0], acc[i][1], acc[i][2], acc[i][3] };
            float4 v1 = { acc[i][4], acc[i][5], acc[i][6], acc[i][7] };
            *(float4*)&g_xr[off]     = v0;
            *(float4*)&g_xr[off + 4] = v1;
        }
    }
}

// ---------------- per-layer gather + epilogue -------------------------------
// h_out[n] = h_in[n] + relu( sum_e invcnt[n,et]*xr[src,et*64:] + xr[n,512:] + b )
__global__ void k_gather(int layer, const float* __restrict__ b, float* __restrict__ dout)
{
    const float* __restrict__ h_in = (layer == 0) ? g_ha : g_hb;
    float* __restrict__ h_out = (layer == 0) ? g_hb : dout;

    int lane = threadIdx.x & 31;
    int n = (blockIdx.x * blockDim.x + threadIdx.x) >> 5;
    if (n >= NN) return;

    int beg = g_rowptr[n];
    int end = g_rowptr[n + 1];
    float2 acc = { 0.f, 0.f };

    int e = beg;
    for (; e + 4 <= end; e += 4) {
        int p0 = g_col[e + 0];
        int p1 = g_col[e + 1];
        int p2 = g_col[e + 2];
        int p3 = g_col[e + 3];
        int et0 = p0 >> 17, et1 = p1 >> 17, et2 = p2 >> 17, et3 = p3 >> 17;
        const float2* q0 = (const float2*)&g_xr[(size_t)(p0 & 0x1FFFF) * CC + (et0 << 6) + 2 * lane];
        const float2* q1 = (const float2*)&g_xr[(size_t)(p1 & 0x1FFFF) * CC + (et1 << 6) + 2 * lane];
        const float2* q2 = (const float2*)&g_xr[(size_t)(p2 & 0x1FFFF) * CC + (et2 << 6) + 2 * lane];
        const float2* q3 = (const float2*)&g_xr[(size_t)(p3 & 0x1FFFF) * CC + (et3 << 6) + 2 * lane];
        float2 v0 = *q0, v1 = *q1, v2 = *q2, v3 = *q3;
        float w0 = g_invcnt[n * RR + et0];
        float w1 = g_invcnt[n * RR + et1];
        float w2 = g_invcnt[n * RR + et2];
        float w3 = g_invcnt[n * RR + et3];
        acc.x = fmaf(w0, v0.x, acc.x); acc.y = fmaf(w0, v0.y, acc.y);
        acc.x = fmaf(w1, v1.x, acc.x); acc.y = fmaf(w1, v1.y, acc.y);
        acc.x = fmaf(w2, v2.x, acc.x); acc.y = fmaf(w2, v2.y, acc.y);
        acc.x = fmaf(w3, v3.x, acc.x); acc.y = fmaf(w3, v3.y, acc.y);
    }
    for (; e < end; e++) {
        int p = g_col[e];
        int et = p >> 17;
        float2 v = *(const float2*)&g_xr[(size_t)(p & 0x1FFFF) * CC + (et << 6) + 2 * lane];
        float w = g_invcnt[n * RR + et];
        acc.x = fmaf(w, v.x, acc.x);
        acc.y = fmaf(w, v.y, acc.y);
    }

    float2 root = *(const float2*)&g_xr[(size_t)n * CC + 512 + 2 * lane];
    float2 bb   = *(const float2*)&b[2 * lane];
    float2 hv   = *(const float2*)&h_in[(size_t)n * 64 + 2 * lane];
    float rx = fmaxf(acc.x + root.x + bb.x, 0.f);
    float ry = fmaxf(acc.y + root.y + bb.y, 0.f);
    float2 o = { hv.x + rx, hv.y + ry };
    *(float2*)&h_out[(size_t)n * 64 + 2 * lane] = o;
}

// ---------------- launch ----------------------------------------------------
extern "C" void kernel_launch(void* const* d_in, const int* in_sizes, int n_in,
                              void* d_out, int out_size)
{
    (void)in_sizes; (void)n_in; (void)out_size;
    // const int*  x         = (const int*)d_in[0];   // x == arange(N): node_emb[x] == node_emb
    const int*   edge_index = (const int*)d_in[1];    // [2, E]
    const int*   edge_type  = (const int*)d_in[2];    // [E]
    const int*   node_type  = (const int*)d_in[3];    // [N]
    const float* props      = (const float*)d_in[4];  // [N, 32]
    const float* node_emb   = (const float*)d_in[5];  // [N, 64]
    const float* type_emb   = (const float*)d_in[6];  // [16, 64]
    const float* pw1        = (const float*)d_in[7];
    const float* pb1        = (const float*)d_in[8];
    const float* pw2        = (const float*)d_in[9];
    const float* pb2        = (const float*)d_in[10];
    const float* W1         = (const float*)d_in[11];
    const float* Wroot1     = (const float*)d_in[12];
    const float* b1         = (const float*)d_in[13];
    const float* W2         = (const float*)d_in[14];
    const float* Wroot2     = (const float*)d_in[15];
    const float* b2         = (const float*)d_in[16];
    float* out = (float*)d_out;

    // h0 embedding
    k_h0<<<1184, 256>>>(node_type, props, node_emb, type_emb, pw1, pb1, pw2, pb2);

    // CSR build (shared by both layers)
    k_zero<<<1024, 256>>>();
    k_count<<<2048, 256>>>(edge_index, edge_type);
    k_bsum<<<SCAN_BLOCKS, 1024>>>();
    k_sscan<<<1, 1>>>();
    k_scan<<<SCAN_BLOCKS, 1024>>>();
    k_place<<<2048, 256>>>(edge_index, edge_type);

    dim3 ggrid((NN + GEMM_BM - 1) / GEMM_BM, 9);

    // layer 1: g_ha -> g_hb
    k_gemm<<<ggrid, 256>>>(0, W1, Wroot1);
    k_gather<<<(NN + 7) / 8, 256>>>(0, b1, out);

    // layer 2: g_hb -> out
    k_gemm<<<ggrid, 256>>>(1, W2, Wroot2);
    k_gather<<<(NN + 7) / 8, 256>>>(1, b2, out);
}

// round 6
// speedup vs baseline: 1.7448x; 1.7448x over previous
#include <cuda_runtime.h>
#include <cuda_bf16.h>
#include <cstdint>

// Problem constants (fixed by the dataset)
constexpr int NN = 100000;   // nodes
constexpr int EE = 1600000;  // edges
constexpr int RR = 8;        // relations
constexpr int DD = 64;       // hidden
constexpr int CC = 576;      // 8*64 relation cols + 64 Wroot cols
constexpr int SCAN_BLOCKS = (NN + 1023) / 1024;  // 98

// ---------------- scratch (static device allocations; no cudaMalloc) -------
__device__ float g_ha[(size_t)NN * DD];
__device__ float g_hb[(size_t)NN * DD];
__device__ float g_xr[(size_t)NN * CC];
__device__ int   g_rowptr[NN + 1];
__device__ int   g_fill[NN];
__device__ int   g_cntR[NN * RR];
__device__ float g_invcnt[NN * RR];
__device__ int   g_col[EE];
__device__ int   g_bsum[128];
// transposed bf16 weight images: [layer][9 tiles][64 rows e][64 cols d]
__device__ __align__(16) unsigned short g_Bhi[2][9 * 4096];
__device__ __align__(16) unsigned short g_Blo[2][9 * 4096];

// ---------------- h0 = node_emb + type_emb[node_type] + MLP(props) ---------
__global__ void k_h0(const int* __restrict__ node_type,
                     const float* __restrict__ props,
                     const float* __restrict__ node_emb,
                     const float* __restrict__ type_emb,
                     const float* __restrict__ pw1, const float* __restrict__ pb1,
                     const float* __restrict__ pw2, const float* __restrict__ pb2)
{
    __shared__ float sw1[32 * 64];
    __shared__ float sw2[64 * 64];
    __shared__ float sb1[64];
    __shared__ float sb2[64];
    __shared__ float ste[16 * 64];
    for (int i = threadIdx.x; i < 32 * 64; i += blockDim.x) sw1[i] = pw1[i];
    for (int i = threadIdx.x; i < 64 * 64; i += blockDim.x) sw2[i] = pw2[i];
    for (int i = threadIdx.x; i < 64; i += blockDim.x) { sb1[i] = pb1[i]; sb2[i] = pb2[i]; }
    for (int i = threadIdx.x; i < 16 * 64; i += blockDim.x) ste[i] = type_emb[i];
    __syncthreads();

    int lane = threadIdx.x & 31;
    int warp = (blockIdx.x * blockDim.x + threadIdx.x) >> 5;
    int nwarps = (gridDim.x * blockDim.x) >> 5;

    for (int n = warp; n < NN; n += nwarps) {
        float pv = props[n * 32 + lane];
        float2 t = { sb1[2 * lane], sb1[2 * lane + 1] };
        #pragma unroll
        for (int k = 0; k < 32; k++) {
            float a = __shfl_sync(0xffffffffu, pv, k);
            float2 w = *(const float2*)&sw1[k * 64 + 2 * lane];
            t.x = fmaf(a, w.x, t.x);
            t.y = fmaf(a, w.y, t.y);
        }
        t.x = fmaxf(t.x, 0.f); t.y = fmaxf(t.y, 0.f);
        float2 o = { sb2[2 * lane], sb2[2 * lane + 1] };
        #pragma unroll
        for (int k = 0; k < 64; k++) {
            float a = __shfl_sync(0xffffffffu, (k & 1) ? t.y : t.x, k >> 1);
            float2 w = *(const float2*)&sw2[k * 64 + 2 * lane];
            o.x = fmaf(a, w.x, o.x);
            o.y = fmaf(a, w.y, o.y);
        }
        int nt = node_type[n];
        float2 e  = *(const float2*)&node_emb[(size_t)n * 64 + 2 * lane];
        float2 te = *(const float2*)&ste[nt * 64 + 2 * lane];
        o.x += e.x + te.x;
        o.y += e.y + te.y;
        *(float2*)&g_ha[(size_t)n * 64 + 2 * lane] = o;
    }
}

// ---------------- weight prep: transpose + bf16 hi/lo split ----------------
// tile t (0..7 = relations, 8 = root): image[t][e][k] = W[t][k][e]
__global__ void k_prepB(const float* __restrict__ W1, const float* __restrict__ Wroot1,
                        const float* __restrict__ W2, const float* __restrict__ Wroot2)
{
    int i = blockIdx.x * blockDim.x + threadIdx.x;
    if (i >= 2 * 9 * 4096) return;
    int layer = i / 36864;
    int rem = i % 36864;
    int t = rem / 4096;
    int e = (rem % 4096) / 64;
    int k = rem & 63;
    const float* W = (layer == 0) ? W1 : W2;
    const float* Wr = (layer == 0) ? Wroot1 : Wroot2;
    float v = (t < 8) ? W[t * 4096 + k * 64 + e] : Wr[k * 64 + e];
    __nv_bfloat16 hi = __float2bfloat16_rn(v);
    __nv_bfloat16 lo = __float2bfloat16_rn(v - __bfloat162float(hi));
    g_Bhi[layer][rem] = __bfloat16_as_ushort(hi);
    g_Blo[layer][rem] = __bfloat16_as_ushort(lo);
}

// ---------------- CSR build -------------------------------------------------
__global__ void k_zero()
{
    int total = NN * RR + NN;
    for (int i = blockIdx.x * blockDim.x + threadIdx.x; i < total; i += gridDim.x * blockDim.x) {
        if (i < NN * RR) g_cntR[i] = 0;
        else             g_fill[i - NN * RR] = 0;
    }
}

__global__ void k_count(const int* __restrict__ ei, const int* __restrict__ et)
{
    for (int e = blockIdx.x * blockDim.x + threadIdx.x; e < EE; e += gridDim.x * blockDim.x) {
        int d = ei[EE + e];
        int r = et[e];
        atomicAdd(&g_cntR[d * RR + r], 1);
    }
}

__global__ void k_bsum()
{
    int n = blockIdx.x * 1024 + threadIdx.x;
    int s = 0;
    if (n < NN) {
        #pragma unroll
        for (int r = 0; r < RR; r++) s += g_cntR[n * RR + r];
    }
    __shared__ int sh[32];
    #pragma unroll
    for (int o = 16; o > 0; o >>= 1) s += __shfl_down_sync(0xffffffffu, s, o);
    if ((threadIdx.x & 31) == 0) sh[threadIdx.x >> 5] = s;
    __syncthreads();
    if (threadIdx.x < 32) {
        int v = sh[threadIdx.x];
        #pragma unroll
        for (int o = 16; o > 0; o >>= 1) v += __shfl_down_sync(0xffffffffu, v, o);
        if (threadIdx.x == 0) g_bsum[blockIdx.x] = v;
    }
}

__global__ void k_sscan()
{
    int acc = 0;
    for (int i = 0; i < SCAN_BLOCKS; i++) {
        int v = g_bsum[i];
        g_bsum[i] = acc;
        acc += v;
    }
}

__global__ void k_scan()
{
    int n = blockIdx.x * 1024 + threadIdx.x;
    int c[RR];
    int s = 0;
    if (n < NN) {
        #pragma unroll
        for (int r = 0; r < RR; r++) { c[r] = g_cntR[n * RR + r]; s += c[r]; }
    }
    int lane = threadIdx.x & 31, w = threadIdx.x >> 5;
    int incl = s;
    #pragma unroll
    for (int o = 1; o < 32; o <<= 1) {
        int v = __shfl_up_sync(0xffffffffu, incl, o);
        if (lane >= o) incl += v;
    }
    __shared__ int wsum[32];
    if (lane == 31) wsum[w] = incl;
    __syncthreads();
    if (threadIdx.x < 32) {
        int v = wsum[threadIdx.x];
        int iv = v;
        #pragma unroll
        for (int o = 1; o < 32; o <<= 1) {
            int u = __shfl_up_sync(0xffffffffu, iv, o);
            if (threadIdx.x >= o) iv += u;
        }
        wsum[threadIdx.x] = iv - v;
    }
    __syncthreads();
    int excl = (incl - s) + wsum[w] + g_bsum[blockIdx.x];
    if (n < NN) {
        g_rowptr[n] = excl;
        #pragma unroll
        for (int r = 0; r < RR; r++)
            g_invcnt[n * RR + r] = 1.0f / (float)(c[r] > 1 ? c[r] : 1);
        if (n == NN - 1) g_rowptr[NN] = excl + s;
    }
}

__global__ void k_place(const int* __restrict__ ei, const int* __restrict__ et)
{
    for (int e = blockIdx.x * blockDim.x + threadIdx.x; e < EE; e += gridDim.x * blockDim.x) {
        int d = ei[EE + e];
        int r = et[e];
        int s = ei[e];
        int pos = g_rowptr[d] + atomicAdd(&g_fill[d], 1);
        g_col[pos] = s | (r << 17);
    }
}

// ---------------- mma.sync GEMM: xr[N,576] = h @ [Wflat | Wroot] -----------
// Split-bf16 3-term product (a_hi*b_hi + a_lo*b_hi + a_hi*b_lo), fp32 accum.
// smem (halfs, padded rows of 72 to kill LDS bank conflicts):
//   A_hi[128][72], A_lo[128][72], B_hi[9*64][72], B_lo[9*64][72]
constexpr int BPAD = 72;
constexpr int SM_A_HI = 0;
constexpr int SM_A_LO = 128 * BPAD;
constexpr int SM_B_HI = 2 * 128 * BPAD;
constexpr int SM_B_LO = SM_B_HI + 9 * 64 * BPAD;
constexpr int SMEM_HALFS = SM_B_LO + 9 * 64 * BPAD;
constexpr int SMEM_DYN = SMEM_HALFS * 2;   // 202752 bytes

__device__ __forceinline__ void mma_bf16(float* c, const uint32_t* a, uint32_t b0, uint32_t b1) {
    asm volatile("mma.sync.aligned.m16n8k16.row.col.f32.bf16.bf16.f32 "
        "{%0,%1,%2,%3}, {%4,%5,%6,%7}, {%8,%9}, {%0,%1,%2,%3};"
        : "+f"(c[0]), "+f"(c[1]), "+f"(c[2]), "+f"(c[3])
        : "r"(a[0]), "r"(a[1]), "r"(a[2]), "r"(a[3]), "r"(b0), "r"(b1));
}

__global__ void __launch_bounds__(256) k_gemm_mma(int layer)
{
    extern __shared__ unsigned short sm[];
    const float* __restrict__ h_in = (layer == 0) ? g_ha : g_hb;
    int tid = threadIdx.x;
    int wid = tid >> 5;
    int lane = tid & 31;
    int mbase = blockIdx.x * 128;

    // ---- copy B images (9*4096 halfs each) into padded smem ----
    {
        const uint32_t* srch = (const uint32_t*)&g_Bhi[layer][0];
        const uint32_t* srcl = (const uint32_t*)&g_Blo[layer][0];
        for (int i = tid; i < 9 * 2048; i += 256) {
            int row = i >> 5;          // 0..575 (tiles contiguous, 64 rows each)
            int cp  = i & 31;          // pair index within row
            uint32_t vh = srch[i];
            uint32_t vl = srcl[i];
            *(uint32_t*)&sm[SM_B_HI + row * BPAD + cp * 2] = vh;
            *(uint32_t*)&sm[SM_B_LO + row * BPAD + cp * 2] = vl;
        }
    }

    // ---- convert A tile (128 rows x 64) to hi/lo bf16 ----
    {
        int row = tid >> 1;
        int c0 = (tid & 1) * 32;
        int g = mbase + row;
        bool valid = (g < NN);
        const float4* hp = (const float4*)&h_in[(size_t)(valid ? g : 0) * 64 + c0];
        #pragma unroll
        for (int j = 0; j < 8; j++) {
            float4 v = valid ? hp[j] : make_float4(0.f, 0.f, 0.f, 0.f);
            float vs[4] = { v.x, v.y, v.z, v.w };
            #pragma unroll
            for (int p = 0; p < 2; p++) {
                float a0 = vs[2 * p], a1 = vs[2 * p + 1];
                __nv_bfloat16 h0 = __float2bfloat16_rn(a0);
                __nv_bfloat16 h1 = __float2bfloat16_rn(a1);
                __nv_bfloat16 l0 = __float2bfloat16_rn(a0 - __bfloat162float(h0));
                __nv_bfloat16 l1 = __float2bfloat16_rn(a1 - __bfloat162float(h1));
                uint32_t uh = (uint32_t)__bfloat16_as_ushort(h0) |
                              ((uint32_t)__bfloat16_as_ushort(h1) << 16);
                uint32_t ul = (uint32_t)__bfloat16_as_ushort(l0) |
                              ((uint32_t)__bfloat16_as_ushort(l1) << 16);
                int c = c0 + j * 4 + 2 * p;
                *(uint32_t*)&sm[SM_A_HI + row * BPAD + c] = uh;
                *(uint32_t*)&sm[SM_A_LO + row * BPAD + c] = ul;
            }
        }
    }
    __syncthreads();

    // ---- fragments ----
    int g8 = lane >> 2;            // 0..7
    int kq = (lane & 3) * 2;       // 0,2,4,6
    int wr = wid * 16;

    uint32_t ahi[4][4], alo[4][4];
    #pragma unroll
    for (int ks = 0; ks < 4; ks++) {
        int kb = ks * 16 + kq;
        ahi[ks][0] = *(const uint32_t*)&sm[SM_A_HI + (wr + g8) * BPAD + kb];
        ahi[ks][1] = *(const uint32_t*)&sm[SM_A_HI + (wr + g8 + 8) * BPAD + kb];
        ahi[ks][2] = *(const uint32_t*)&sm[SM_A_HI + (wr + g8) * BPAD + kb + 8];
        ahi[ks][3] = *(const uint32_t*)&sm[SM_A_HI + (wr + g8 + 8) * BPAD + kb + 8];
        alo[ks][0] = *(const uint32_t*)&sm[SM_A_LO + (wr + g8) * BPAD + kb];
        alo[ks][1] = *(const uint32_t*)&sm[SM_A_LO + (wr + g8 + 8) * BPAD + kb];
        alo[ks][2] = *(const uint32_t*)&sm[SM_A_LO + (wr + g8) * BPAD + kb + 8];
        alo[ks][3] = *(const uint32_t*)&sm[SM_A_LO + (wr + g8 + 8) * BPAD + kb + 8];
    }

    int rowA = mbase + wr + g8;
    int rowB = rowA + 8;
    bool vA = (rowA < NN), vB = (rowB < NN);
    float* outA = &g_xr[(size_t)(vA ? rowA : 0) * CC];
    float* outB = &g_xr[(size_t)(vB ? rowB : 0) * CC];
    int n0 = (lane & 3) * 2;

    #pragma unroll 1
    for (int r = 0; r < 9; r++) {
        float acc[8][4];
        #pragma unroll
        for (int nt = 0; nt < 8; nt++)
            #pragma unroll
            for (int j = 0; j < 4; j++) acc[nt][j] = 0.f;

        #pragma unroll
        for (int ks = 0; ks < 4; ks++) {
            int kb = ks * 16 + kq;
            #pragma unroll
            for (int nt = 0; nt < 8; nt++) {
                int brow = r * 64 + nt * 8 + g8;
                uint32_t bh0 = *(const uint32_t*)&sm[SM_B_HI + brow * BPAD + kb];
                uint32_t bh1 = *(const uint32_t*)&sm[SM_B_HI + brow * BPAD + kb + 8];
                uint32_t bl0 = *(const uint32_t*)&sm[SM_B_LO + brow * BPAD + kb];
                uint32_t bl1 = *(const uint32_t*)&sm[SM_B_LO + brow * BPAD + kb + 8];
                mma_bf16(acc[nt], ahi[ks], bh0, bh1);
                mma_bf16(acc[nt], alo[ks], bh0, bh1);
                mma_bf16(acc[nt], ahi[ks], bl0, bl1);
            }
        }

        #pragma unroll
        for (int nt = 0; nt < 8; nt++) {
            int col = r * 64 + nt * 8 + n0;
            if (vA) *(float2*)&outA[col] = make_float2(acc[nt][0], acc[nt][1]);
            if (vB) *(float2*)&outB[col] = make_float2(acc[nt][2], acc[nt][3]);
        }
    }
}

// ---------------- per-layer gather + epilogue -------------------------------
__global__ void k_gather(int layer, const float* __restrict__ b, float* __restrict__ dout)
{
    const float* __restrict__ h_in = (layer == 0) ? g_ha : g_hb;
    float* __restrict__ h_out = (layer == 0) ? g_hb : dout;

    int lane = threadIdx.x & 31;
    int n = (blockIdx.x * blockDim.x + threadIdx.x) >> 5;
    if (n >= NN) return;

    int beg = g_rowptr[n];
    int end = g_rowptr[n + 1];
    float2 acc = { 0.f, 0.f };

    int e = beg;
    for (; e + 4 <= end; e += 4) {
        int p0 = g_col[e + 0];
        int p1 = g_col[e + 1];
        int p2 = g_col[e + 2];
        int p3 = g_col[e + 3];
        int et0 = p0 >> 17, et1 = p1 >> 17, et2 = p2 >> 17, et3 = p3 >> 17;
        const float2* q0 = (const float2*)&g_xr[(size_t)(p0 & 0x1FFFF) * CC + (et0 << 6) + 2 * lane];
        const float2* q1 = (const float2*)&g_xr[(size_t)(p1 & 0x1FFFF) * CC + (et1 << 6) + 2 * lane];
        const float2* q2 = (const float2*)&g_xr[(size_t)(p2 & 0x1FFFF) * CC + (et2 << 6) + 2 * lane];
        const float2* q3 = (const float2*)&g_xr[(size_t)(p3 & 0x1FFFF) * CC + (et3 << 6) + 2 * lane];
        float2 v0 = *q0, v1 = *q1, v2 = *q2, v3 = *q3;
        float w0 = g_invcnt[n * RR + et0];
        float w1 = g_invcnt[n * RR + et1];
        float w2 = g_invcnt[n * RR + et2];
        float w3 = g_invcnt[n * RR + et3];
        acc.x = fmaf(w0, v0.x, acc.x); acc.y = fmaf(w0, v0.y, acc.y);
        acc.x = fmaf(w1, v1.x, acc.x); acc.y = fmaf(w1, v1.y, acc.y);
        acc.x = fmaf(w2, v2.x, acc.x); acc.y = fmaf(w2, v2.y, acc.y);
        acc.x = fmaf(w3, v3.x, acc.x); acc.y = fmaf(w3, v3.y, acc.y);
    }
    for (; e < end; e++) {
        int p = g_col[e];
        int et = p >> 17;
        float2 v = *(const float2*)&g_xr[(size_t)(p & 0x1FFFF) * CC + (et << 6) + 2 * lane];
        float w = g_invcnt[n * RR + et];
        acc.x = fmaf(w, v.x, acc.x);
        acc.y = fmaf(w, v.y, acc.y);
    }

    float2 root = *(const float2*)&g_xr[(size_t)n * CC + 512 + 2 * lane];
    float2 bb   = *(const float2*)&b[2 * lane];
    float2 hv   = *(const float2*)&h_in[(size_t)n * 64 + 2 * lane];
    float rx = fmaxf(acc.x + root.x + bb.x, 0.f);
    float ry = fmaxf(acc.y + root.y + bb.y, 0.f);
    float2 o = { hv.x + rx, hv.y + ry };
    *(float2*)&h_out[(size_t)n * 64 + 2 * lane] = o;
}

// ---------------- launch ----------------------------------------------------
extern "C" void kernel_launch(void* const* d_in, const int* in_sizes, int n_in,
                              void* d_out, int out_size)
{
    (void)in_sizes; (void)n_in; (void)out_size;
    const int*   edge_index = (const int*)d_in[1];
    const int*   edge_type  = (const int*)d_in[2];
    const int*   node_type  = (const int*)d_in[3];
    const float* props      = (const float*)d_in[4];
    const float* node_emb   = (const float*)d_in[5];
    const float* type_emb   = (const float*)d_in[6];
    const float* pw1        = (const float*)d_in[7];
    const float* pb1        = (const float*)d_in[8];
    const float* pw2        = (const float*)d_in[9];
    const float* pb2        = (const float*)d_in[10];
    const float* W1         = (const float*)d_in[11];
    const float* Wroot1     = (const float*)d_in[12];
    const float* b1         = (const float*)d_in[13];
    const float* W2         = (const float*)d_in[14];
    const float* Wroot2     = (const float*)d_in[15];
    const float* b2         = (const float*)d_in[16];
    float* out = (float*)d_out;

    cudaFuncSetAttribute(k_gemm_mma, cudaFuncAttributeMaxDynamicSharedMemorySize, SMEM_DYN);

    // h0 embedding + weight prep
    k_h0<<<1184, 256>>>(node_type, props, node_emb, type_emb, pw1, pb1, pw2, pb2);
    k_prepB<<<(2 * 9 * 4096 + 255) / 256, 256>>>(W1, Wroot1, W2, Wroot2);

    // CSR build (shared by both layers)
    k_zero<<<1024, 256>>>();
    k_count<<<2048, 256>>>(edge_index, edge_type);
    k_bsum<<<SCAN_BLOCKS, 1024>>>();
    k_sscan<<<1, 1>>>();
    k_scan<<<SCAN_BLOCKS, 1024>>>();
    k_place<<<2048, 256>>>(edge_index, edge_type);

    int gemm_blocks = (NN + 127) / 128;   // 782

    // layer 1: g_ha -> g_hb
    k_gemm_mma<<<gemm_blocks, 256, SMEM_DYN>>>(0);
    k_gather<<<(NN + 7) / 8, 256>>>(0, b1, out);

    // layer 2: g_hb -> out
    k_gemm_mma<<<gemm_blocks, 256, SMEM_DYN>>>(1);
    k_gather<<<(NN + 7) / 8, 256>>>(1, b2, out);
}